// round 2
// baseline (speedup 1.0000x reference)
#include <cuda_runtime.h>
#include <cstdint>
#include <float.h>

#define N_NODES 50000
#define E_RAW   800000
#define E_TOT   850000   // E_RAW + N_NODES self loops
#define H1      15
#define F1      120      // H1*8
#define DIN     128
#define F2      32

#define FULL 0xFFFFFFFFu

// ---------------- scratch (device globals; no allocation allowed) ----------------
__device__ int      g_src[(size_t)E_TOT];
__device__ int      g_dst[(size_t)E_TOT];
__device__ unsigned g_is64;                            // edge dtype flag
__device__ float    g_xl1[(size_t)N_NODES * F1];
__device__ float    g_xr1[(size_t)N_NODES * F1];
__device__ float    g_e1[(size_t)E_TOT * H1];          // logits, then exp'd values
__device__ unsigned g_emax1[(size_t)N_NODES * H1];     // order-preserving-encoded max
__device__ float    g_den1[(size_t)N_NODES * H1];
__device__ float    g_h[(size_t)N_NODES * F1];         // layer-1 output / layer-2 input
__device__ float    g_hl2[(size_t)N_NODES * F2];
__device__ float    g_hr2[(size_t)N_NODES * F2];
__device__ float    g_e2[(size_t)E_TOT];
__device__ unsigned g_emax2[(size_t)N_NODES];
__device__ float    g_den2[(size_t)N_NODES];
__device__ float    g_out2[(size_t)N_NODES * F2];

// order-preserving float<->uint for atomicMax on signed floats
__device__ __forceinline__ unsigned f2u(float f) {
    unsigned u = __float_as_uint(f);
    return (u & 0x80000000u) ? ~u : (u | 0x80000000u);
}
__device__ __forceinline__ float u2f(unsigned u) {
    return __uint_as_float((u & 0x80000000u) ? (u & 0x7FFFFFFFu) : ~u);
}
#define ENC_NEG_INF 0x007FFFFFu   // f2u(-inf)

__device__ __forceinline__ float lrelu(float v) { return v > 0.f ? v : 0.2f * v; }

// ---------------- edge dtype detection ----------------
// Safe window: in_sizes[1] = 1.6M elements -> at least 1.6M int32 words exist.
// int64 edges (<50000): every odd word is 0. int32 edges: odd words are ~random ids.
__global__ void k_detect(const int* __restrict__ ei_raw) {
    unsigned acc = 0;
    for (int i = blockIdx.x * blockDim.x + threadIdx.x; i < E_RAW; i += gridDim.x * blockDim.x)
        acc |= (unsigned)ei_raw[2 * i + 1];
    // reduce within warp then atomically OR
#pragma unroll
    for (int o = 16; o; o >>= 1) acc |= __shfl_xor_sync(FULL, acc, o);
    if ((threadIdx.x & 31) == 0 && acc) atomicOr(&g_is64, 1u);
}

// ---------------- normalize edges to int32 + append self loops ----------------
__global__ void k_convert(const int* __restrict__ ei_raw) {
    int e = blockIdx.x * blockDim.x + threadIdx.x;
    if (e >= E_TOT) return;
    if (e >= E_RAW) {
        g_src[e] = e - E_RAW;
        g_dst[e] = e - E_RAW;
        return;
    }
    if (g_is64) {
        g_src[e] = ei_raw[e];                 // int32 layout: [src x E][dst x E]
        g_dst[e] = ei_raw[E_RAW + e];
    } else {
        g_src[e] = ei_raw[e];
        g_dst[e] = ei_raw[E_RAW + e];
    }
}
// NOTE: for int64 the low words of value v sit at word index 2v offsets; handled below.
__global__ void k_convert64(const int* __restrict__ ei_raw) {
    int e = blockIdx.x * blockDim.x + threadIdx.x;
    if (e >= E_RAW) return;
    if (g_is64) return;            // flag==0 means int64 (all odd words were zero)
    ;                              // no-op when int32
}
// Single conversion kernel that branches on the flag correctly:
__global__ void k_convert_all(const int* __restrict__ ei_raw) {
    int e = blockIdx.x * blockDim.x + threadIdx.x;
    if (e >= E_TOT) return;
    if (e >= E_RAW) {
        g_src[e] = e - E_RAW;
        g_dst[e] = e - E_RAW;
        return;
    }
    if (g_is64) {                  // int32 data (odd words nonzero)
        g_src[e] = ei_raw[e];
        g_dst[e] = ei_raw[E_RAW + e];
    } else {                       // int64 data: low word at 2*index
        g_src[e] = ei_raw[2 * e];
        g_dst[e] = ei_raw[2 * (E_RAW + e)];
    }
}

// ---------------- init ----------------
__global__ void k_init() {
    int i = blockIdx.x * blockDim.x + threadIdx.x;
    if (i == 0) g_is64 = 0u;
    if (i < N_NODES * F1) g_h[i] = 0.f;
    if (i < N_NODES * H1) { g_emax1[i] = ENC_NEG_INF; g_den1[i] = 0.f; }
    if (i < N_NODES * F2) g_out2[i] = 0.f;
    if (i < N_NODES)      { g_emax2[i] = ENC_NEG_INF; g_den2[i] = 0.f; }
}

// ---------------- GEMM1: xl1 = x@W1l, xr1 = x@W1r  (warp handles 4 nodes) ----------------
__global__ void k_gemm1(const float* __restrict__ x,
                        const float* __restrict__ Wl,
                        const float* __restrict__ Wr) {
    int warp = (blockIdx.x * blockDim.x + threadIdx.x) >> 5;
    int lane = threadIdx.x & 31;
    int nb = warp * 4;
    if (nb >= N_NODES) return;

    float4 xv0 = *(const float4*)(x + (size_t)(nb + 0) * DIN + lane * 4);
    float4 xv1 = *(const float4*)(x + (size_t)(nb + 1) * DIN + lane * 4);
    float4 xv2 = *(const float4*)(x + (size_t)(nb + 2) * DIN + lane * 4);
    float4 xv3 = *(const float4*)(x + (size_t)(nb + 3) * DIN + lane * 4);

    int g = lane < 30 ? lane : 0;   // lanes 30,31 compute garbage, never store
    const float4* wl4 = (const float4*)Wl;   // row k -> index k*30 + g
    const float4* wr4 = (const float4*)Wr;

    float4 al[4], ar[4];
#pragma unroll
    for (int j = 0; j < 4; j++) { al[j] = make_float4(0,0,0,0); ar[j] = make_float4(0,0,0,0); }

#pragma unroll
    for (int k = 0; k < DIN; k += 4) {
        int sl = k >> 2;
        float b0x = __shfl_sync(FULL, xv0.x, sl), b0y = __shfl_sync(FULL, xv0.y, sl),
              b0z = __shfl_sync(FULL, xv0.z, sl), b0w = __shfl_sync(FULL, xv0.w, sl);
        float b1x = __shfl_sync(FULL, xv1.x, sl), b1y = __shfl_sync(FULL, xv1.y, sl),
              b1z = __shfl_sync(FULL, xv1.z, sl), b1w = __shfl_sync(FULL, xv1.w, sl);
        float b2x = __shfl_sync(FULL, xv2.x, sl), b2y = __shfl_sync(FULL, xv2.y, sl),
              b2z = __shfl_sync(FULL, xv2.z, sl), b2w = __shfl_sync(FULL, xv2.w, sl);
        float b3x = __shfl_sync(FULL, xv3.x, sl), b3y = __shfl_sync(FULL, xv3.y, sl),
              b3z = __shfl_sync(FULL, xv3.z, sl), b3w = __shfl_sync(FULL, xv3.w, sl);
        float xk[4][4] = {{b0x,b0y,b0z,b0w},{b1x,b1y,b1z,b1w},{b2x,b2y,b2z,b2w},{b3x,b3y,b3z,b3w}};
#pragma unroll
        for (int kk = 0; kk < 4; kk++) {
            float4 w1 = __ldg(&wl4[(size_t)(k + kk) * 30 + g]);
            float4 w2 = __ldg(&wr4[(size_t)(k + kk) * 30 + g]);
#pragma unroll
            for (int j = 0; j < 4; j++) {
                float s = xk[j][kk];
                al[j].x += s * w1.x; al[j].y += s * w1.y; al[j].z += s * w1.z; al[j].w += s * w1.w;
                ar[j].x += s * w2.x; ar[j].y += s * w2.y; ar[j].z += s * w2.z; ar[j].w += s * w2.w;
            }
        }
    }
    if (lane < 30) {
#pragma unroll
        for (int j = 0; j < 4; j++) {
            *(float4*)(g_xl1 + (size_t)(nb + j) * F1 + lane * 4) = al[j];
            *(float4*)(g_xr1 + (size_t)(nb + j) * F1 + lane * 4) = ar[j];
        }
    }
}

// ---------------- layer1 edge logits + segment max (warp per edge) ----------------
__global__ void k_logits1(const float* __restrict__ att) {
    int e = (blockIdx.x * blockDim.x + threadIdx.x) >> 5;
    int lane = threadIdx.x & 31;
    if (e >= E_TOT) return;
    int src = g_src[e], dst = g_dst[e];

    int g = lane < 30 ? lane : 0;
    float4 a = __ldg((const float4*)(g_xl1 + (size_t)src * F1) + g);
    float4 b = __ldg((const float4*)(g_xr1 + (size_t)dst * F1) + g);
    float4 at = __ldg((const float4*)att + g);
    float p = lrelu(a.x + b.x) * at.x + lrelu(a.y + b.y) * at.y +
              lrelu(a.z + b.z) * at.z + lrelu(a.w + b.w) * at.w;
    float p2 = __shfl_down_sync(FULL, p, 1);
    if (lane < 30 && (lane & 1) == 0) {
        float v = p + p2;
        int h = lane >> 1;
        g_e1[(size_t)e * H1 + h] = v;
        atomicMax(&g_emax1[(size_t)dst * H1 + h], f2u(v));
    }
}

// ---------------- layer1 exp + denom (thread per (edge,head)) ----------------
__global__ void k_softmax1() {
    int idx = blockIdx.x * blockDim.x + threadIdx.x;
    if (idx >= E_TOT * H1) return;
    int e = idx / H1;
    int h = idx - e * H1;
    int dst = g_dst[e];
    float m = u2f(g_emax1[(size_t)dst * H1 + h]);
    float ee = expf(g_e1[idx] - m);
    g_e1[idx] = ee;
    atomicAdd(&g_den1[(size_t)dst * H1 + h], ee);
}

// ---------------- layer1 aggregate: g_h[dst] += alpha * xl[src] (warp per edge) ----------------
__global__ void k_agg1() {
    int e = (blockIdx.x * blockDim.x + threadIdx.x) >> 5;
    int lane = threadIdx.x & 31;
    if (e >= E_TOT) return;
    int src = g_src[e], dst = g_dst[e];

    float r = 0.f;
    if (lane < H1)
        r = g_e1[(size_t)e * H1 + lane] / g_den1[(size_t)dst * H1 + lane];
    float alpha = __shfl_sync(FULL, r, lane >> 1);
    if (lane < 30) {
        float4 a = __ldg((const float4*)(g_xl1 + (size_t)src * F1) + lane);
        float* o = g_h + (size_t)dst * F1 + lane * 4;
        atomicAdd(o + 0, alpha * a.x);
        atomicAdd(o + 1, alpha * a.y);
        atomicAdd(o + 2, alpha * a.z);
        atomicAdd(o + 3, alpha * a.w);
    }
}

// ---------------- bias + ELU ----------------
__global__ void k_bias_elu(const float* __restrict__ b1) {
    int i = blockIdx.x * blockDim.x + threadIdx.x;
    if (i >= N_NODES * F1) return;
    float v = g_h[i] + __ldg(&b1[i % F1]);
    g_h[i] = v > 0.f ? v : expm1f(v);
}

// ---------------- GEMM2: hl2 = h@W2l, hr2 = h@W2r (warp handles 4 nodes, lane=col) ----------------
__global__ void k_gemm2(const float* __restrict__ Wl, const float* __restrict__ Wr) {
    int warp = (blockIdx.x * blockDim.x + threadIdx.x) >> 5;
    int lane = threadIdx.x & 31;
    int nb = warp * 4;
    if (nb >= N_NODES) return;

    int g = lane < 30 ? lane : 0;  // row holder lanes (120 = 30*4)
    float4 xv0 = *(const float4*)(g_h + (size_t)(nb + 0) * F1 + g * 4);
    float4 xv1 = *(const float4*)(g_h + (size_t)(nb + 1) * F1 + g * 4);
    float4 xv2 = *(const float4*)(g_h + (size_t)(nb + 2) * F1 + g * 4);
    float4 xv3 = *(const float4*)(g_h + (size_t)(nb + 3) * F1 + g * 4);

    float accl[4] = {0,0,0,0}, accr[4] = {0,0,0,0};
#pragma unroll
    for (int k = 0; k < F1; k += 4) {
        int sl = k >> 2;
        float b0x = __shfl_sync(FULL, xv0.x, sl), b0y = __shfl_sync(FULL, xv0.y, sl),
              b0z = __shfl_sync(FULL, xv0.z, sl), b0w = __shfl_sync(FULL, xv0.w, sl);
        float b1x = __shfl_sync(FULL, xv1.x, sl), b1y = __shfl_sync(FULL, xv1.y, sl),
              b1z = __shfl_sync(FULL, xv1.z, sl), b1w = __shfl_sync(FULL, xv1.w, sl);
        float b2x = __shfl_sync(FULL, xv2.x, sl), b2y = __shfl_sync(FULL, xv2.y, sl),
              b2z = __shfl_sync(FULL, xv2.z, sl), b2w = __shfl_sync(FULL, xv2.w, sl);
        float b3x = __shfl_sync(FULL, xv3.x, sl), b3y = __shfl_sync(FULL, xv3.y, sl),
              b3z = __shfl_sync(FULL, xv3.z, sl), b3w = __shfl_sync(FULL, xv3.w, sl);
        float xk[4][4] = {{b0x,b0y,b0z,b0w},{b1x,b1y,b1z,b1w},{b2x,b2y,b2z,b2w},{b3x,b3y,b3z,b3w}};
#pragma unroll
        for (int kk = 0; kk < 4; kk++) {
            float w1 = __ldg(&Wl[(size_t)(k + kk) * F2 + lane]);
            float w2 = __ldg(&Wr[(size_t)(k + kk) * F2 + lane]);
#pragma unroll
            for (int j = 0; j < 4; j++) {
                accl[j] += xk[j][kk] * w1;
                accr[j] += xk[j][kk] * w2;
            }
        }
    }
#pragma unroll
    for (int j = 0; j < 4; j++) {
        g_hl2[(size_t)(nb + j) * F2 + lane] = accl[j];
        g_hr2[(size_t)(nb + j) * F2 + lane] = accr[j];
    }
}

// ---------------- layer2 edge logits + max (8 lanes per edge, 4 edges/warp) ----------------
__global__ void k_logits2(const float* __restrict__ att) {
    int warp = (blockIdx.x * blockDim.x + threadIdx.x) >> 5;
    int lane = threadIdx.x & 31;
    int grp = lane >> 3, q = lane & 7;
    int e = warp * 4 + grp;
    bool valid = (e < E_TOT);
    int src = 0, dst = 0;
    if (valid) { src = g_src[e]; dst = g_dst[e]; }

    float4 a = __ldg((const float4*)(g_hl2 + (size_t)src * F2) + q);
    float4 b = __ldg((const float4*)(g_hr2 + (size_t)dst * F2) + q);
    float4 at = __ldg((const float4*)att + q);
    float p = lrelu(a.x + b.x) * at.x + lrelu(a.y + b.y) * at.y +
              lrelu(a.z + b.z) * at.z + lrelu(a.w + b.w) * at.w;
    p += __shfl_down_sync(FULL, p, 4, 8);
    p += __shfl_down_sync(FULL, p, 2, 8);
    p += __shfl_down_sync(FULL, p, 1, 8);
    if (valid && q == 0) {
        g_e2[e] = p;
        atomicMax(&g_emax2[dst], f2u(p));
    }
}

// ---------------- layer2 exp + denom ----------------
__global__ void k_softmax2() {
    int e = blockIdx.x * blockDim.x + threadIdx.x;
    if (e >= E_TOT) return;
    int dst = g_dst[e];
    float ee = expf(g_e2[e] - u2f(g_emax2[dst]));
    g_e2[e] = ee;
    atomicAdd(&g_den2[dst], ee);
}

// ---------------- layer2 aggregate ----------------
__global__ void k_agg2() {
    int warp = (blockIdx.x * blockDim.x + threadIdx.x) >> 5;
    int lane = threadIdx.x & 31;
    int grp = lane >> 3, q = lane & 7;
    int e = warp * 4 + grp;
    if (e >= E_TOT) return;
    int src = g_src[e], dst = g_dst[e];
    float alpha = g_e2[e] / g_den2[dst];
    float4 a = __ldg((const float4*)(g_hl2 + (size_t)src * F2) + q);
    float* o = g_out2 + (size_t)dst * F2 + q * 4;
    atomicAdd(o + 0, alpha * a.x);
    atomicAdd(o + 1, alpha * a.y);
    atomicAdd(o + 2, alpha * a.z);
    atomicAdd(o + 3, alpha * a.w);
}

// ---------------- bias + log_softmax, write both outputs (warp per node) ----------------
__global__ void k_final(const float* __restrict__ b2, float* __restrict__ out) {
    int n = (blockIdx.x * blockDim.x + threadIdx.x) >> 5;
    int lane = threadIdx.x & 31;
    if (n >= N_NODES) return;
    float v = g_out2[(size_t)n * F2 + lane] + __ldg(&b2[lane]);
    float m = v;
#pragma unroll
    for (int o = 16; o; o >>= 1) m = fmaxf(m, __shfl_xor_sync(FULL, m, o));
    float ex = expf(v - m);
    float s = ex;
#pragma unroll
    for (int o = 16; o; o >>= 1) s += __shfl_xor_sync(FULL, s, o);
    float ls = v - m - logf(s);
    out[(size_t)n * F2 + lane] = v;
    out[(size_t)N_NODES * F2 + (size_t)n * F2 + lane] = ls;
}

// ---------------- launcher ----------------
extern "C" void kernel_launch(void* const* d_in, const int* in_sizes, int n_in,
                              void* d_out, int out_size) {
    const float* x    = (const float*)d_in[0];
    const int*   ei   = (const int*)d_in[1];     // dtype detected at runtime
    const float* W1l  = (const float*)d_in[2];
    const float* W1r  = (const float*)d_in[3];
    const float* att1 = (const float*)d_in[4];
    const float* b1   = (const float*)d_in[5];
    const float* W2l  = (const float*)d_in[6];
    const float* W2r  = (const float*)d_in[7];
    const float* att2 = (const float*)d_in[8];
    const float* b2   = (const float*)d_in[9];
    float* out = (float*)d_out;

    k_init<<<(N_NODES * F1 + 255) / 256, 256>>>();
    k_detect<<<512, 256>>>(ei);
    k_convert_all<<<(E_TOT + 255) / 256, 256>>>(ei);
    k_gemm1<<<((N_NODES / 4) * 32 + 255) / 256, 256>>>(x, W1l, W1r);
    k_logits1<<<(E_TOT * 32) / 256, 256>>>(att1);
    k_softmax1<<<(E_TOT * H1 + 255) / 256, 256>>>();
    k_agg1<<<(E_TOT * 32) / 256, 256>>>();
    k_bias_elu<<<(N_NODES * F1 + 255) / 256, 256>>>(b1);
    k_gemm2<<<((N_NODES / 4) * 32 + 255) / 256, 256>>>(W2l, W2r);
    k_logits2<<<(((E_TOT + 3) / 4) * 32 + 255) / 256, 256>>>(att2);
    k_softmax2<<<(E_TOT + 255) / 256, 256>>>();
    k_agg2<<<(((E_TOT + 3) / 4) * 32 + 255) / 256, 256>>>();
    k_final<<<(N_NODES * 32 + 255) / 256, 256>>>(b2, out);
}

// round 3
// speedup vs baseline: 1.2780x; 1.2780x over previous
#include <cuda_runtime.h>
#include <cstdint>
#include <float.h>

#define N_NODES 50000
#define E_RAW   800000
#define E_TOT   850000   // E_RAW + N_NODES self loops
#define H1      15
#define F1      120      // H1*8
#define DIN     128
#define F2      32

#define FULL 0xFFFFFFFFu

// ---------------- scratch (device globals; no allocation allowed) ----------------
__device__ int      g_src[(size_t)E_TOT];
__device__ int      g_dst[(size_t)E_TOT];
__device__ unsigned g_is64;                            // edge dtype flag
__device__ float    g_xl1[(size_t)N_NODES * F1];
__device__ float    g_xr1[(size_t)N_NODES * F1];
__device__ float    g_e1[(size_t)E_TOT * H1];          // logits
__device__ unsigned g_emax1[(size_t)N_NODES * H1];     // order-preserving-encoded max
__device__ float    g_den1[(size_t)N_NODES * H1];
__device__ float    g_h[(size_t)N_NODES * F1];         // layer-1 unnormalized accum -> activations
__device__ float    g_hl2[(size_t)N_NODES * F2];
__device__ float    g_hr2[(size_t)N_NODES * F2];
__device__ float    g_e2[(size_t)E_TOT];
__device__ unsigned g_emax2[(size_t)N_NODES];
__device__ float    g_den2[(size_t)N_NODES];
__device__ float    g_out2[(size_t)N_NODES * F2];

// order-preserving float<->uint for atomicMax on signed floats
__device__ __forceinline__ unsigned f2u(float f) {
    unsigned u = __float_as_uint(f);
    return (u & 0x80000000u) ? ~u : (u | 0x80000000u);
}
__device__ __forceinline__ float u2f(unsigned u) {
    return __uint_as_float((u & 0x80000000u) ? (u & 0x7FFFFFFFu) : ~u);
}
#define ENC_NEG_INF 0x007FFFFFu   // f2u(-inf)

__device__ __forceinline__ float lrelu(float v) { return v > 0.f ? v : 0.2f * v; }

// vectorized global float4 reduction (PTX 8.1+, sm_90+)
__device__ __forceinline__ void red_add_v4(float* p, float a, float b, float c, float d) {
    asm volatile("red.global.add.v4.f32 [%0], {%1, %2, %3, %4};"
                 :: "l"(p), "f"(a), "f"(b), "f"(c), "f"(d) : "memory");
}

// ---------------- edge dtype detection ----------------
// int64 edges (<50000): every odd 32-bit word is 0. int32 edges: odd words ~random ids.
__global__ void k_detect(const int* __restrict__ ei_raw) {
    unsigned acc = 0;
    for (int i = blockIdx.x * blockDim.x + threadIdx.x; i < E_RAW; i += gridDim.x * blockDim.x)
        acc |= (unsigned)ei_raw[2 * i + 1];
#pragma unroll
    for (int o = 16; o; o >>= 1) acc |= __shfl_xor_sync(FULL, acc, o);
    if ((threadIdx.x & 31) == 0 && acc) atomicOr(&g_is64, 1u);
}

// ---------------- normalize edges to int32 + append self loops ----------------
__global__ void k_convert_all(const int* __restrict__ ei_raw) {
    int e = blockIdx.x * blockDim.x + threadIdx.x;
    if (e >= E_TOT) return;
    if (e >= E_RAW) {
        g_src[e] = e - E_RAW;
        g_dst[e] = e - E_RAW;
        return;
    }
    if (g_is64) {                  // flag set -> data is int32
        g_src[e] = ei_raw[e];
        g_dst[e] = ei_raw[E_RAW + e];
    } else {                       // int64 data: low word at 2*index
        g_src[e] = ei_raw[2 * e];
        g_dst[e] = ei_raw[2 * (E_RAW + e)];
    }
}

// ---------------- init ----------------
__global__ void k_init() {
    int i = blockIdx.x * blockDim.x + threadIdx.x;
    if (i == 0) g_is64 = 0u;
    if (i < N_NODES * F1) g_h[i] = 0.f;
    if (i < N_NODES * H1) { g_emax1[i] = ENC_NEG_INF; g_den1[i] = 0.f; }
    if (i < N_NODES * F2) g_out2[i] = 0.f;
    if (i < N_NODES)      { g_emax2[i] = ENC_NEG_INF; g_den2[i] = 0.f; }
}

// ---------------- GEMM1: xl1 = x@W1l, xr1 = x@W1r  (warp handles 8 nodes) ----------------
__global__ void k_gemm1(const float* __restrict__ x,
                        const float* __restrict__ Wl,
                        const float* __restrict__ Wr) {
    int warp = (blockIdx.x * blockDim.x + threadIdx.x) >> 5;
    int lane = threadIdx.x & 31;
    int nb = warp * 8;
    if (nb >= N_NODES) return;

    float4 xv[8];
#pragma unroll
    for (int j = 0; j < 8; j++)
        xv[j] = *(const float4*)(x + (size_t)(nb + j) * DIN + lane * 4);

    int g = lane < 30 ? lane : 0;   // lanes 30,31 compute garbage, never store
    const float4* wl4 = (const float4*)Wl;   // row k -> index k*30 + g
    const float4* wr4 = (const float4*)Wr;

    float4 al[8], ar[8];
#pragma unroll
    for (int j = 0; j < 8; j++) { al[j] = make_float4(0,0,0,0); ar[j] = make_float4(0,0,0,0); }

#pragma unroll 4
    for (int k = 0; k < DIN; k += 4) {
        int sl = k >> 2;
        float xk[8][4];
#pragma unroll
        for (int j = 0; j < 8; j++) {
            xk[j][0] = __shfl_sync(FULL, xv[j].x, sl);
            xk[j][1] = __shfl_sync(FULL, xv[j].y, sl);
            xk[j][2] = __shfl_sync(FULL, xv[j].z, sl);
            xk[j][3] = __shfl_sync(FULL, xv[j].w, sl);
        }
#pragma unroll
        for (int kk = 0; kk < 4; kk++) {
            float4 w1 = __ldg(&wl4[(size_t)(k + kk) * 30 + g]);
            float4 w2 = __ldg(&wr4[(size_t)(k + kk) * 30 + g]);
#pragma unroll
            for (int j = 0; j < 8; j++) {
                float s = xk[j][kk];
                al[j].x += s * w1.x; al[j].y += s * w1.y; al[j].z += s * w1.z; al[j].w += s * w1.w;
                ar[j].x += s * w2.x; ar[j].y += s * w2.y; ar[j].z += s * w2.z; ar[j].w += s * w2.w;
            }
        }
    }
    if (lane < 30) {
#pragma unroll
        for (int j = 0; j < 8; j++) {
            *(float4*)(g_xl1 + (size_t)(nb + j) * F1 + lane * 4) = al[j];
            *(float4*)(g_xr1 + (size_t)(nb + j) * F1 + lane * 4) = ar[j];
        }
    }
}

// ---------------- layer1 edge logits + segment max (warp per edge) ----------------
__global__ void k_logits1(const float* __restrict__ att) {
    int e = (blockIdx.x * blockDim.x + threadIdx.x) >> 5;
    int lane = threadIdx.x & 31;
    if (e >= E_TOT) return;
    int src = g_src[e], dst = g_dst[e];

    int g = lane < 30 ? lane : 0;
    float4 a = __ldg((const float4*)(g_xl1 + (size_t)src * F1) + g);
    float4 b = __ldg((const float4*)(g_xr1 + (size_t)dst * F1) + g);
    float4 at = __ldg((const float4*)att + g);
    float p = lrelu(a.x + b.x) * at.x + lrelu(a.y + b.y) * at.y +
              lrelu(a.z + b.z) * at.z + lrelu(a.w + b.w) * at.w;
    float p2 = __shfl_down_sync(FULL, p, 1);
    if (lane < 30 && (lane & 1) == 0) {
        float v = p + p2;
        int h = lane >> 1;
        g_e1[(size_t)e * H1 + h] = v;
        atomicMax(&g_emax1[(size_t)dst * H1 + h], f2u(v));
    }
}

// ---------------- layer1 fused exp + denom + aggregate (warp per edge) ----------------
// accumulates UNNORMALIZED exp*xl into g_h; division by den happens in k_bias_elu
__global__ void k_agg1() {
    int e = (blockIdx.x * blockDim.x + threadIdx.x) >> 5;
    int lane = threadIdx.x & 31;
    if (e >= E_TOT) return;
    int src = g_src[e], dst = g_dst[e];

    float ee = 0.f;
    if (lane < H1) {
        float m = u2f(g_emax1[(size_t)dst * H1 + lane]);
        ee = expf(g_e1[(size_t)e * H1 + lane] - m);
        atomicAdd(&g_den1[(size_t)dst * H1 + lane], ee);
    }
    float w = __shfl_sync(FULL, ee, lane >> 1);   // channel lane c -> head c/2
    if (lane < 30) {
        float4 a = __ldg((const float4*)(g_xl1 + (size_t)src * F1) + lane);
        red_add_v4(g_h + (size_t)dst * F1 + lane * 4, w * a.x, w * a.y, w * a.z, w * a.w);
    }
}

// ---------------- normalize + bias + ELU ----------------
__global__ void k_bias_elu(const float* __restrict__ b1) {
    int i = blockIdx.x * blockDim.x + threadIdx.x;
    if (i >= N_NODES * F1) return;
    int col = i % F1;
    int n = i / F1;
    int h = col >> 3;
    float v = g_h[i] / g_den1[(size_t)n * H1 + h] + __ldg(&b1[col]);
    g_h[i] = v > 0.f ? v : expm1f(v);
}

// ---------------- GEMM2: hl2 = h@W2l, hr2 = h@W2r (warp handles 4 nodes, lane=col) ----------------
__global__ void k_gemm2(const float* __restrict__ Wl, const float* __restrict__ Wr) {
    int warp = (blockIdx.x * blockDim.x + threadIdx.x) >> 5;
    int lane = threadIdx.x & 31;
    int nb = warp * 4;
    if (nb >= N_NODES) return;

    int g = lane < 30 ? lane : 0;  // row holder lanes (120 = 30*4)
    float4 xv0 = *(const float4*)(g_h + (size_t)(nb + 0) * F1 + g * 4);
    float4 xv1 = *(const float4*)(g_h + (size_t)(nb + 1) * F1 + g * 4);
    float4 xv2 = *(const float4*)(g_h + (size_t)(nb + 2) * F1 + g * 4);
    float4 xv3 = *(const float4*)(g_h + (size_t)(nb + 3) * F1 + g * 4);

    float accl[4] = {0,0,0,0}, accr[4] = {0,0,0,0};
#pragma unroll
    for (int k = 0; k < F1; k += 4) {
        int sl = k >> 2;
        float b0x = __shfl_sync(FULL, xv0.x, sl), b0y = __shfl_sync(FULL, xv0.y, sl),
              b0z = __shfl_sync(FULL, xv0.z, sl), b0w = __shfl_sync(FULL, xv0.w, sl);
        float b1x = __shfl_sync(FULL, xv1.x, sl), b1y = __shfl_sync(FULL, xv1.y, sl),
              b1z = __shfl_sync(FULL, xv1.z, sl), b1w = __shfl_sync(FULL, xv1.w, sl);
        float b2x = __shfl_sync(FULL, xv2.x, sl), b2y = __shfl_sync(FULL, xv2.y, sl),
              b2z = __shfl_sync(FULL, xv2.z, sl), b2w = __shfl_sync(FULL, xv2.w, sl);
        float b3x = __shfl_sync(FULL, xv3.x, sl), b3y = __shfl_sync(FULL, xv3.y, sl),
              b3z = __shfl_sync(FULL, xv3.z, sl), b3w = __shfl_sync(FULL, xv3.w, sl);
        float xk[4][4] = {{b0x,b0y,b0z,b0w},{b1x,b1y,b1z,b1w},{b2x,b2y,b2z,b2w},{b3x,b3y,b3z,b3w}};
#pragma unroll
        for (int kk = 0; kk < 4; kk++) {
            float w1 = __ldg(&Wl[(size_t)(k + kk) * F2 + lane]);
            float w2 = __ldg(&Wr[(size_t)(k + kk) * F2 + lane]);
#pragma unroll
            for (int j = 0; j < 4; j++) {
                accl[j] += xk[j][kk] * w1;
                accr[j] += xk[j][kk] * w2;
            }
        }
    }
#pragma unroll
    for (int j = 0; j < 4; j++) {
        g_hl2[(size_t)(nb + j) * F2 + lane] = accl[j];
        g_hr2[(size_t)(nb + j) * F2 + lane] = accr[j];
    }
}

// ---------------- layer2 edge logits + max (8 lanes per edge, 4 edges/warp) ----------------
__global__ void k_logits2(const float* __restrict__ att) {
    int warp = (blockIdx.x * blockDim.x + threadIdx.x) >> 5;
    int lane = threadIdx.x & 31;
    int grp = lane >> 3, q = lane & 7;
    int e = warp * 4 + grp;
    bool valid = (e < E_TOT);
    int src = 0, dst = 0;
    if (valid) { src = g_src[e]; dst = g_dst[e]; }

    float4 a = __ldg((const float4*)(g_hl2 + (size_t)src * F2) + q);
    float4 b = __ldg((const float4*)(g_hr2 + (size_t)dst * F2) + q);
    float4 at = __ldg((const float4*)att + q);
    float p = lrelu(a.x + b.x) * at.x + lrelu(a.y + b.y) * at.y +
              lrelu(a.z + b.z) * at.z + lrelu(a.w + b.w) * at.w;
    p += __shfl_down_sync(FULL, p, 4, 8);
    p += __shfl_down_sync(FULL, p, 2, 8);
    p += __shfl_down_sync(FULL, p, 1, 8);
    if (valid && q == 0) {
        g_e2[e] = p;
        atomicMax(&g_emax2[dst], f2u(p));
    }
}

// ---------------- layer2 fused exp + denom + aggregate ----------------
__global__ void k_agg2() {
    int warp = (blockIdx.x * blockDim.x + threadIdx.x) >> 5;
    int lane = threadIdx.x & 31;
    int grp = lane >> 3, q = lane & 7;
    int e = warp * 4 + grp;
    if (e >= E_TOT) return;
    int src = g_src[e], dst = g_dst[e];

    float ee = 0.f;
    if (q == 0) {
        ee = expf(g_e2[e] - u2f(g_emax2[dst]));
        atomicAdd(&g_den2[dst], ee);
    }
    float w = __shfl_sync(FULL, ee, grp << 3);
    float4 a = __ldg((const float4*)(g_hl2 + (size_t)src * F2) + q);
    red_add_v4(g_out2 + (size_t)dst * F2 + q * 4, w * a.x, w * a.y, w * a.z, w * a.w);
}

// ---------------- normalize + bias + log_softmax, write both outputs (warp per node) ----------------
__global__ void k_final(const float* __restrict__ b2, float* __restrict__ out) {
    int n = (blockIdx.x * blockDim.x + threadIdx.x) >> 5;
    int lane = threadIdx.x & 31;
    if (n >= N_NODES) return;
    float v = g_out2[(size_t)n * F2 + lane] / g_den2[n] + __ldg(&b2[lane]);
    float m = v;
#pragma unroll
    for (int o = 16; o; o >>= 1) m = fmaxf(m, __shfl_xor_sync(FULL, m, o));
    float ex = expf(v - m);
    float s = ex;
#pragma unroll
    for (int o = 16; o; o >>= 1) s += __shfl_xor_sync(FULL, s, o);
    float ls = v - m - logf(s);
    out[(size_t)n * F2 + lane] = v;
    out[(size_t)N_NODES * F2 + (size_t)n * F2 + lane] = ls;
}

// ---------------- launcher ----------------
extern "C" void kernel_launch(void* const* d_in, const int* in_sizes, int n_in,
                              void* d_out, int out_size) {
    const float* x    = (const float*)d_in[0];
    const int*   ei   = (const int*)d_in[1];     // dtype detected at runtime
    const float* W1l  = (const float*)d_in[2];
    const float* W1r  = (const float*)d_in[3];
    const float* att1 = (const float*)d_in[4];
    const float* b1   = (const float*)d_in[5];
    const float* W2l  = (const float*)d_in[6];
    const float* W2r  = (const float*)d_in[7];
    const float* att2 = (const float*)d_in[8];
    const float* b2   = (const float*)d_in[9];
    float* out = (float*)d_out;

    k_init<<<(N_NODES * F1 + 255) / 256, 256>>>();
    k_detect<<<512, 256>>>(ei);
    k_convert_all<<<(E_TOT + 255) / 256, 256>>>(ei);
    k_gemm1<<<(((N_NODES + 7) / 8) * 32 + 255) / 256, 256>>>(x, W1l, W1r);
    k_logits1<<<(E_TOT * 32) / 256, 256>>>(att1);
    k_agg1<<<(E_TOT * 32) / 256, 256>>>();
    k_bias_elu<<<(N_NODES * F1 + 255) / 256, 256>>>(b1);
    k_gemm2<<<((N_NODES / 4) * 32 + 255) / 256, 256>>>(W2l, W2r);
    k_logits2<<<(((E_TOT + 3) / 4) * 32 + 255) / 256, 256>>>(att2);
    k_agg2<<<(((E_TOT + 3) / 4) * 32 + 255) / 256, 256>>>();
    k_final<<<(N_NODES * 32 + 255) / 256, 256>>>(b2, out);
}

// round 4
// speedup vs baseline: 1.9233x; 1.5049x over previous
#include <cuda_runtime.h>
#include <cstdint>
#include <float.h>

#define N_NODES 50000
#define E_RAW   800000
#define E_TOT   850000   // E_RAW + N_NODES self loops
#define H1      15
#define F1      120      // H1*8
#define DIN     128
#define F2      32

#define FULL 0xFFFFFFFFu

// ---------------- scratch (device globals; no allocation allowed) ----------------
__device__ int      g_src[(size_t)E_TOT];
__device__ int      g_dst[(size_t)E_TOT];
__device__ unsigned g_is64;                            // edge dtype flag
__device__ float    g_xl1[(size_t)N_NODES * F1];
__device__ float    g_xr1[(size_t)N_NODES * F1];
__device__ float    g_den1[(size_t)N_NODES * H1];
__device__ float    g_h[(size_t)N_NODES * F1];         // unnormalized accum -> activations
__device__ float    g_hl2[(size_t)N_NODES * F2];
__device__ float    g_hr2[(size_t)N_NODES * F2];
__device__ float    g_den2[(size_t)N_NODES];
__device__ float    g_out2[(size_t)N_NODES * F2];

__device__ __forceinline__ float lrelu(float v) { return v > 0.f ? v : 0.2f * v; }

// vectorized global float4 reduction (PTX 8.1+, sm_90+)
__device__ __forceinline__ void red_add_v4(float* p, float a, float b, float c, float d) {
    asm volatile("red.global.add.v4.f32 [%0], {%1, %2, %3, %4};"
                 :: "l"(p), "f"(a), "f"(b), "f"(c), "f"(d) : "memory");
}

// ---------------- edge dtype detection ----------------
// int64 edges (<50000): every odd 32-bit word is 0. int32 edges: odd words ~random ids.
__global__ void k_detect(const int* __restrict__ ei_raw) {
    unsigned acc = 0;
    for (int i = blockIdx.x * blockDim.x + threadIdx.x; i < E_RAW; i += gridDim.x * blockDim.x)
        acc |= (unsigned)ei_raw[2 * i + 1];
#pragma unroll
    for (int o = 16; o; o >>= 1) acc |= __shfl_xor_sync(FULL, acc, o);
    if ((threadIdx.x & 31) == 0 && acc) atomicOr(&g_is64, 1u);
}

// ---------------- normalize edges to int32 + append self loops ----------------
__global__ void k_convert_all(const int* __restrict__ ei_raw) {
    int e = blockIdx.x * blockDim.x + threadIdx.x;
    if (e >= E_TOT) return;
    if (e >= E_RAW) {
        g_src[e] = e - E_RAW;
        g_dst[e] = e - E_RAW;
        return;
    }
    if (g_is64) {                  // flag set -> data is int32
        g_src[e] = ei_raw[e];
        g_dst[e] = ei_raw[E_RAW + e];
    } else {                       // int64 data: low word at 2*index
        g_src[e] = ei_raw[2 * e];
        g_dst[e] = ei_raw[2 * (E_RAW + e)];
    }
}

// ---------------- init ----------------
__global__ void k_init() {
    int i = blockIdx.x * blockDim.x + threadIdx.x;
    if (i == 0) g_is64 = 0u;
    if (i < N_NODES * F1) g_h[i] = 0.f;
    if (i < N_NODES * H1) g_den1[i] = 0.f;
    if (i < N_NODES * F2) g_out2[i] = 0.f;
    if (i < N_NODES)      g_den2[i] = 0.f;
}

// ---------------- GEMM1: xl1 = x@W1l, xr1 = x@W1r  (warp handles 4 nodes) ----------------
__global__ void k_gemm1(const float* __restrict__ x,
                        const float* __restrict__ Wl,
                        const float* __restrict__ Wr) {
    int warp = (blockIdx.x * blockDim.x + threadIdx.x) >> 5;
    int lane = threadIdx.x & 31;
    int nb = warp * 4;
    if (nb >= N_NODES) return;

    float4 xv0 = *(const float4*)(x + (size_t)(nb + 0) * DIN + lane * 4);
    float4 xv1 = *(const float4*)(x + (size_t)(nb + 1) * DIN + lane * 4);
    float4 xv2 = *(const float4*)(x + (size_t)(nb + 2) * DIN + lane * 4);
    float4 xv3 = *(const float4*)(x + (size_t)(nb + 3) * DIN + lane * 4);

    int g = lane < 30 ? lane : 0;   // lanes 30,31 compute garbage, never store
    const float4* wl4 = (const float4*)Wl;   // row k -> index k*30 + g
    const float4* wr4 = (const float4*)Wr;

    float4 al[4], ar[4];
#pragma unroll
    for (int j = 0; j < 4; j++) { al[j] = make_float4(0,0,0,0); ar[j] = make_float4(0,0,0,0); }

#pragma unroll
    for (int k = 0; k < DIN; k += 4) {
        int sl = k >> 2;
        float b0x = __shfl_sync(FULL, xv0.x, sl), b0y = __shfl_sync(FULL, xv0.y, sl),
              b0z = __shfl_sync(FULL, xv0.z, sl), b0w = __shfl_sync(FULL, xv0.w, sl);
        float b1x = __shfl_sync(FULL, xv1.x, sl), b1y = __shfl_sync(FULL, xv1.y, sl),
              b1z = __shfl_sync(FULL, xv1.z, sl), b1w = __shfl_sync(FULL, xv1.w, sl);
        float b2x = __shfl_sync(FULL, xv2.x, sl), b2y = __shfl_sync(FULL, xv2.y, sl),
              b2z = __shfl_sync(FULL, xv2.z, sl), b2w = __shfl_sync(FULL, xv2.w, sl);
        float b3x = __shfl_sync(FULL, xv3.x, sl), b3y = __shfl_sync(FULL, xv3.y, sl),
              b3z = __shfl_sync(FULL, xv3.z, sl), b3w = __shfl_sync(FULL, xv3.w, sl);
        float xk[4][4] = {{b0x,b0y,b0z,b0w},{b1x,b1y,b1z,b1w},{b2x,b2y,b2z,b2w},{b3x,b3y,b3z,b3w}};
#pragma unroll
        for (int kk = 0; kk < 4; kk++) {
            float4 w1 = __ldg(&wl4[(size_t)(k + kk) * 30 + g]);
            float4 w2 = __ldg(&wr4[(size_t)(k + kk) * 30 + g]);
#pragma unroll
            for (int j = 0; j < 4; j++) {
                float s = xk[j][kk];
                al[j].x += s * w1.x; al[j].y += s * w1.y; al[j].z += s * w1.z; al[j].w += s * w1.w;
                ar[j].x += s * w2.x; ar[j].y += s * w2.y; ar[j].z += s * w2.z; ar[j].w += s * w2.w;
            }
        }
    }
    if (lane < 30) {
#pragma unroll
        for (int j = 0; j < 4; j++) {
            *(float4*)(g_xl1 + (size_t)(nb + j) * F1 + lane * 4) = al[j];
            *(float4*)(g_xr1 + (size_t)(nb + j) * F1 + lane * 4) = ar[j];
        }
    }
}

// ---------------- layer1 FULLY FUSED edge pass (warp per edge) ----------------
// e = <lrelu(xl[src]+xr[dst]), att>; w = exp(e) (no max subtraction: softmax is
// shift-invariant and |e| = O(1) here); den += w; h[dst] += w * xl[src]
__global__ void k_edge1(const float* __restrict__ att) {
    int e = (blockIdx.x * blockDim.x + threadIdx.x) >> 5;
    int lane = threadIdx.x & 31;
    if (e >= E_TOT) return;
    int src = g_src[e], dst = g_dst[e];

    int g = lane < 30 ? lane : 0;
    float4 a = __ldg((const float4*)(g_xl1 + (size_t)src * F1) + g);
    float4 b = __ldg((const float4*)(g_xr1 + (size_t)dst * F1) + g);
    float4 at = __ldg((const float4*)att + g);
    float p = lrelu(a.x + b.x) * at.x + lrelu(a.y + b.y) * at.y +
              lrelu(a.z + b.z) * at.z + lrelu(a.w + b.w) * at.w;
    float p2 = __shfl_down_sync(FULL, p, 1);
    float ee = 0.f;
    if (lane < 30 && (lane & 1) == 0) {           // head h at lane 2h
        ee = expf(p + p2);
        atomicAdd(&g_den1[(size_t)dst * H1 + (lane >> 1)], ee);
    }
    float w = __shfl_sync(FULL, ee, lane & 30);   // channel lane c -> head at lane c&~1
    if (lane < 30)
        red_add_v4(g_h + (size_t)dst * F1 + lane * 4, w * a.x, w * a.y, w * a.z, w * a.w);
}

// ---------------- normalize + bias + ELU ----------------
__global__ void k_bias_elu(const float* __restrict__ b1) {
    int i = blockIdx.x * blockDim.x + threadIdx.x;
    if (i >= N_NODES * F1) return;
    int col = i % F1;
    int n = i / F1;
    int h = col >> 3;
    float v = g_h[i] / g_den1[(size_t)n * H1 + h] + __ldg(&b1[col]);
    g_h[i] = v > 0.f ? v : expm1f(v);
}

// ---------------- GEMM2: hl2 = h@W2l, hr2 = h@W2r (warp handles 4 nodes, lane=col) ----------------
__global__ void k_gemm2(const float* __restrict__ Wl, const float* __restrict__ Wr) {
    int warp = (blockIdx.x * blockDim.x + threadIdx.x) >> 5;
    int lane = threadIdx.x & 31;
    int nb = warp * 4;
    if (nb >= N_NODES) return;

    int g = lane < 30 ? lane : 0;  // row holder lanes (120 = 30*4)
    float4 xv0 = *(const float4*)(g_h + (size_t)(nb + 0) * F1 + g * 4);
    float4 xv1 = *(const float4*)(g_h + (size_t)(nb + 1) * F1 + g * 4);
    float4 xv2 = *(const float4*)(g_h + (size_t)(nb + 2) * F1 + g * 4);
    float4 xv3 = *(const float4*)(g_h + (size_t)(nb + 3) * F1 + g * 4);

    float accl[4] = {0,0,0,0}, accr[4] = {0,0,0,0};
#pragma unroll
    for (int k = 0; k < F1; k += 4) {
        int sl = k >> 2;
        float b0x = __shfl_sync(FULL, xv0.x, sl), b0y = __shfl_sync(FULL, xv0.y, sl),
              b0z = __shfl_sync(FULL, xv0.z, sl), b0w = __shfl_sync(FULL, xv0.w, sl);
        float b1x = __shfl_sync(FULL, xv1.x, sl), b1y = __shfl_sync(FULL, xv1.y, sl),
              b1z = __shfl_sync(FULL, xv1.z, sl), b1w = __shfl_sync(FULL, xv1.w, sl);
        float b2x = __shfl_sync(FULL, xv2.x, sl), b2y = __shfl_sync(FULL, xv2.y, sl),
              b2z = __shfl_sync(FULL, xv2.z, sl), b2w = __shfl_sync(FULL, xv2.w, sl);
        float b3x = __shfl_sync(FULL, xv3.x, sl), b3y = __shfl_sync(FULL, xv3.y, sl),
              b3z = __shfl_sync(FULL, xv3.z, sl), b3w = __shfl_sync(FULL, xv3.w, sl);
        float xk[4][4] = {{b0x,b0y,b0z,b0w},{b1x,b1y,b1z,b1w},{b2x,b2y,b2z,b2w},{b3x,b3y,b3z,b3w}};
#pragma unroll
        for (int kk = 0; kk < 4; kk++) {
            float w1 = __ldg(&Wl[(size_t)(k + kk) * F2 + lane]);
            float w2 = __ldg(&Wr[(size_t)(k + kk) * F2 + lane]);
#pragma unroll
            for (int j = 0; j < 4; j++) {
                accl[j] += xk[j][kk] * w1;
                accr[j] += xk[j][kk] * w2;
            }
        }
    }
#pragma unroll
    for (int j = 0; j < 4; j++) {
        g_hl2[(size_t)(nb + j) * F2 + lane] = accl[j];
        g_hr2[(size_t)(nb + j) * F2 + lane] = accr[j];
    }
}

// ---------------- layer2 FULLY FUSED edge pass (8 lanes per edge, 4 edges/warp) ----------------
__global__ void k_edge2(const float* __restrict__ att) {
    int warp = (blockIdx.x * blockDim.x + threadIdx.x) >> 5;
    int lane = threadIdx.x & 31;
    int grp = lane >> 3, q = lane & 7;
    int e = warp * 4 + grp;
    bool valid = (e < E_TOT);
    int src = 0, dst = 0;
    if (valid) { src = g_src[e]; dst = g_dst[e]; }

    float4 a = __ldg((const float4*)(g_hl2 + (size_t)src * F2) + q);
    float4 b = __ldg((const float4*)(g_hr2 + (size_t)dst * F2) + q);
    float4 at = __ldg((const float4*)att + q);
    float p = lrelu(a.x + b.x) * at.x + lrelu(a.y + b.y) * at.y +
              lrelu(a.z + b.z) * at.z + lrelu(a.w + b.w) * at.w;
    p += __shfl_down_sync(FULL, p, 4, 8);
    p += __shfl_down_sync(FULL, p, 2, 8);
    p += __shfl_down_sync(FULL, p, 1, 8);
    float ee = 0.f;
    if (valid && q == 0) {
        ee = expf(p);
        atomicAdd(&g_den2[dst], ee);
    }
    float w = __shfl_sync(FULL, ee, grp << 3);
    if (valid)
        red_add_v4(g_out2 + (size_t)dst * F2 + q * 4, w * a.x, w * a.y, w * a.z, w * a.w);
}

// ---------------- normalize + bias + log_softmax, write both outputs (warp per node) ----------------
__global__ void k_final(const float* __restrict__ b2, float* __restrict__ out) {
    int n = (blockIdx.x * blockDim.x + threadIdx.x) >> 5;
    int lane = threadIdx.x & 31;
    if (n >= N_NODES) return;
    float v = g_out2[(size_t)n * F2 + lane] / g_den2[n] + __ldg(&b2[lane]);
    float m = v;
#pragma unroll
    for (int o = 16; o; o >>= 1) m = fmaxf(m, __shfl_xor_sync(FULL, m, o));
    float ex = expf(v - m);
    float s = ex;
#pragma unroll
    for (int o = 16; o; o >>= 1) s += __shfl_xor_sync(FULL, s, o);
    float ls = v - m - logf(s);
    out[(size_t)n * F2 + lane] = v;
    out[(size_t)N_NODES * F2 + (size_t)n * F2 + lane] = ls;
}

// ---------------- launcher ----------------
extern "C" void kernel_launch(void* const* d_in, const int* in_sizes, int n_in,
                              void* d_out, int out_size) {
    const float* x    = (const float*)d_in[0];
    const int*   ei   = (const int*)d_in[1];     // dtype detected at runtime
    const float* W1l  = (const float*)d_in[2];
    const float* W1r  = (const float*)d_in[3];
    const float* att1 = (const float*)d_in[4];
    const float* b1   = (const float*)d_in[5];
    const float* W2l  = (const float*)d_in[6];
    const float* W2r  = (const float*)d_in[7];
    const float* att2 = (const float*)d_in[8];
    const float* b2   = (const float*)d_in[9];
    float* out = (float*)d_out;

    k_init<<<(N_NODES * F1 + 255) / 256, 256>>>();
    k_detect<<<512, 256>>>(ei);
    k_convert_all<<<(E_TOT + 255) / 256, 256>>>(ei);
    k_gemm1<<<((N_NODES / 4) * 32 + 255) / 256, 256>>>(x, W1l, W1r);
    k_edge1<<<(E_TOT * 32) / 256, 256>>>(att1);
    k_bias_elu<<<(N_NODES * F1 + 255) / 256, 256>>>(b1);
    k_gemm2<<<((N_NODES / 4) * 32 + 255) / 256, 256>>>(W2l, W2r);
    k_edge2<<<(((E_TOT + 3) / 4) * 32 + 255) / 256, 256>>>(att2);
    k_final<<<(N_NODES * 32 + 255) / 256, 256>>>(b2, out);
}

// round 5
// speedup vs baseline: 1.9789x; 1.0289x over previous
#include <cuda_runtime.h>
#include <cstdint>
#include <float.h>

#define N_NODES 50000
#define E_RAW   800000
#define E_TOT   850000   // E_RAW + N_NODES self loops
#define H1      15
#define F1      120      // H1*8
#define DIN     128
#define F2      32

#define FULL 0xFFFFFFFFu

// ---------------- scratch (device globals; no allocation allowed) ----------------
__device__ int      g_src[(size_t)E_TOT];
__device__ int      g_dst[(size_t)E_TOT];
__device__ unsigned g_is64;                            // edge dtype flag
__device__ float    g_xl1[(size_t)N_NODES * F1];
__device__ float    g_xr1[(size_t)N_NODES * F1];
__device__ float    g_den1[(size_t)N_NODES * H1];
__device__ float    g_h[(size_t)N_NODES * F1];         // unnormalized layer-1 accum
__device__ float    g_hl2[(size_t)N_NODES * F2];
__device__ float    g_hr2[(size_t)N_NODES * F2];
__device__ float    g_den2[(size_t)N_NODES];
__device__ float    g_out2[(size_t)N_NODES * F2];

__device__ __forceinline__ float lrelu(float v) { return v > 0.f ? v : 0.2f * v; }

// vectorized global float4 reduction (PTX 8.1+, sm_90+)
__device__ __forceinline__ void red_add_v4(float* p, float a, float b, float c, float d) {
    asm volatile("red.global.add.v4.f32 [%0], {%1, %2, %3, %4};"
                 :: "l"(p), "f"(a), "f"(b), "f"(c), "f"(d) : "memory");
}

// ---------------- edge dtype detection ----------------
// int64 edges (<50000): every odd 32-bit word is 0. int32 edges: odd words ~random ids.
__global__ void k_detect(const int* __restrict__ ei_raw) {
    unsigned acc = 0;
    for (int i = blockIdx.x * blockDim.x + threadIdx.x; i < E_RAW; i += gridDim.x * blockDim.x)
        acc |= (unsigned)ei_raw[2 * i + 1];
#pragma unroll
    for (int o = 16; o; o >>= 1) acc |= __shfl_xor_sync(FULL, acc, o);
    if ((threadIdx.x & 31) == 0 && acc) atomicOr(&g_is64, 1u);
}

// ---------------- normalize edges to int32 + append self loops ----------------
__global__ void k_convert_all(const int* __restrict__ ei_raw) {
    int e = blockIdx.x * blockDim.x + threadIdx.x;
    if (e >= E_TOT) return;
    if (e >= E_RAW) {
        g_src[e] = e - E_RAW;
        g_dst[e] = e - E_RAW;
        return;
    }
    if (g_is64) {                  // flag set -> data is int32
        g_src[e] = ei_raw[e];
        g_dst[e] = ei_raw[E_RAW + e];
    } else {                       // int64 data: low word at 2*index
        g_src[e] = ei_raw[2 * e];
        g_dst[e] = ei_raw[2 * (E_RAW + e)];
    }
}

// ---------------- init ----------------
__global__ void k_init() {
    int i = blockIdx.x * blockDim.x + threadIdx.x;
    if (i == 0) g_is64 = 0u;
    if (i < N_NODES * F1) g_h[i] = 0.f;
    if (i < N_NODES * H1) g_den1[i] = 0.f;
    if (i < N_NODES * F2) g_out2[i] = 0.f;
    if (i < N_NODES)      g_den2[i] = 0.f;
}

// ---------------- GEMM1: warp = 8 nodes x ONE matrix (Wl or Wr) ----------------
__global__ void k_gemm1(const float* __restrict__ x,
                        const float* __restrict__ Wl,
                        const float* __restrict__ Wr) {
    int gwarp = (blockIdx.x * blockDim.x + threadIdx.x) >> 5;
    int lane = threadIdx.x & 31;
    int mat = gwarp & 1;
    int nb = (gwarp >> 1) * 8;
    if (nb >= N_NODES) return;

    const float4* w4 = (const float4*)(mat ? Wr : Wl);  // row k -> index k*30 + g
    float* outp = mat ? g_xr1 : g_xl1;

    float4 xv[8];
#pragma unroll
    for (int j = 0; j < 8; j++)
        xv[j] = *(const float4*)(x + (size_t)(nb + j) * DIN + lane * 4);

    int g = lane < 30 ? lane : 0;   // lanes 30,31 compute garbage, never store

    float4 acc[8];
#pragma unroll
    for (int j = 0; j < 8; j++) acc[j] = make_float4(0, 0, 0, 0);

#pragma unroll 4
    for (int k = 0; k < DIN; k += 4) {
        int sl = k >> 2;
#pragma unroll
        for (int kk = 0; kk < 4; kk++) {
            float4 w = __ldg(&w4[(size_t)(k + kk) * 30 + g]);
            float xs[8];
#pragma unroll
            for (int j = 0; j < 8; j++) {
                float c = (kk == 0) ? xv[j].x : (kk == 1) ? xv[j].y : (kk == 2) ? xv[j].z : xv[j].w;
                xs[j] = __shfl_sync(FULL, c, sl);
            }
#pragma unroll
            for (int j = 0; j < 8; j++) {
                acc[j].x += xs[j] * w.x; acc[j].y += xs[j] * w.y;
                acc[j].z += xs[j] * w.z; acc[j].w += xs[j] * w.w;
            }
        }
    }
    if (lane < 30) {
#pragma unroll
        for (int j = 0; j < 8; j++)
            *(float4*)(outp + (size_t)(nb + j) * F1 + lane * 4) = acc[j];
    }
}

// ---------------- layer1 FULLY FUSED edge pass (warp per edge) ----------------
// w = exp(<lrelu(xl[src]+xr[dst]), att>)  (no max subtraction; logits are O(1))
// den[dst] += w; h[dst] += w * xl[src]
__global__ void k_edge1(const float* __restrict__ att) {
    int e = (blockIdx.x * blockDim.x + threadIdx.x) >> 5;
    int lane = threadIdx.x & 31;
    if (e >= E_TOT) return;
    int src = g_src[e], dst = g_dst[e];

    int g = lane < 30 ? lane : 0;
    float4 a = __ldg((const float4*)(g_xl1 + (size_t)src * F1) + g);
    float4 b = __ldg((const float4*)(g_xr1 + (size_t)dst * F1) + g);
    float4 at = __ldg((const float4*)att + g);
    float p = lrelu(a.x + b.x) * at.x + lrelu(a.y + b.y) * at.y +
              lrelu(a.z + b.z) * at.z + lrelu(a.w + b.w) * at.w;
    float p2 = __shfl_down_sync(FULL, p, 1);
    float ee = 0.f;
    if (lane < 30 && (lane & 1) == 0) {           // head h at lane 2h
        ee = expf(p + p2);
        atomicAdd(&g_den1[(size_t)dst * H1 + (lane >> 1)], ee);
    }
    float w = __shfl_sync(FULL, ee, lane & 30);   // channel lane c -> head at lane c&~1
    if (lane < 30)
        red_add_v4(g_h + (size_t)dst * F1 + lane * 4, w * a.x, w * a.y, w * a.z, w * a.w);
}

// ---------------- GEMM2: warp = 8 nodes x ONE matrix; fused normalize+bias+ELU ----------------
__global__ void k_gemm2(const float* __restrict__ Wl, const float* __restrict__ Wr,
                        const float* __restrict__ b1) {
    int gwarp = (blockIdx.x * blockDim.x + threadIdx.x) >> 5;
    int lane = threadIdx.x & 31;
    int mat = gwarp & 1;
    int nb = (gwarp >> 1) * 8;
    if (nb >= N_NODES) return;

    const float* W = mat ? Wr : Wl;   // [F1, F2] row-major, lane = output col
    float* outp = mat ? g_hr2 : g_hl2;

    int g = lane < 30 ? lane : 0;     // row-holder lanes (120 = 30*4)
    // cols 4g..4g+3 never cross an 8-boundary -> single head index g>>1
    float4 bv = __ldg((const float4*)b1 + g);

    float4 xv[8];
#pragma unroll
    for (int j = 0; j < 8; j++) {
        float4 v = *(const float4*)(g_h + (size_t)(nb + j) * F1 + g * 4);
        float d = 1.f / g_den1[(size_t)(nb + j) * H1 + (g >> 1)];
        v.x = v.x * d + bv.x; v.y = v.y * d + bv.y;
        v.z = v.z * d + bv.z; v.w = v.w * d + bv.w;
        v.x = v.x > 0.f ? v.x : expm1f(v.x);
        v.y = v.y > 0.f ? v.y : expm1f(v.y);
        v.z = v.z > 0.f ? v.z : expm1f(v.z);
        v.w = v.w > 0.f ? v.w : expm1f(v.w);
        xv[j] = v;
    }

    float acc[8] = {0, 0, 0, 0, 0, 0, 0, 0};
#pragma unroll 4
    for (int k = 0; k < F1; k += 4) {
        int sl = k >> 2;
#pragma unroll
        for (int kk = 0; kk < 4; kk++) {
            float w = __ldg(&W[(size_t)(k + kk) * F2 + lane]);
            float xs[8];
#pragma unroll
            for (int j = 0; j < 8; j++) {
                float c = (kk == 0) ? xv[j].x : (kk == 1) ? xv[j].y : (kk == 2) ? xv[j].z : xv[j].w;
                xs[j] = __shfl_sync(FULL, c, sl);
            }
#pragma unroll
            for (int j = 0; j < 8; j++) acc[j] += xs[j] * w;
        }
    }
#pragma unroll
    for (int j = 0; j < 8; j++)
        outp[(size_t)(nb + j) * F2 + lane] = acc[j];
}

// ---------------- layer2 FULLY FUSED edge pass (8 lanes per edge, 4 edges/warp) ----------------
__global__ void k_edge2(const float* __restrict__ att) {
    int warp = (blockIdx.x * blockDim.x + threadIdx.x) >> 5;
    int lane = threadIdx.x & 31;
    int grp = lane >> 3, q = lane & 7;
    int e = warp * 4 + grp;
    bool valid = (e < E_TOT);
    int src = 0, dst = 0;
    if (valid) { src = g_src[e]; dst = g_dst[e]; }

    float4 a = __ldg((const float4*)(g_hl2 + (size_t)src * F2) + q);
    float4 b = __ldg((const float4*)(g_hr2 + (size_t)dst * F2) + q);
    float4 at = __ldg((const float4*)att + q);
    float p = lrelu(a.x + b.x) * at.x + lrelu(a.y + b.y) * at.y +
              lrelu(a.z + b.z) * at.z + lrelu(a.w + b.w) * at.w;
    p += __shfl_down_sync(FULL, p, 4, 8);
    p += __shfl_down_sync(FULL, p, 2, 8);
    p += __shfl_down_sync(FULL, p, 1, 8);
    float ee = 0.f;
    if (valid && q == 0) {
        ee = expf(p);
        atomicAdd(&g_den2[dst], ee);
    }
    float w = __shfl_sync(FULL, ee, grp << 3);
    if (valid)
        red_add_v4(g_out2 + (size_t)dst * F2 + q * 4, w * a.x, w * a.y, w * a.z, w * a.w);
}

// ---------------- normalize + bias + log_softmax, write both outputs (warp per node) ----------------
__global__ void k_final(const float* __restrict__ b2, float* __restrict__ out) {
    int n = (blockIdx.x * blockDim.x + threadIdx.x) >> 5;
    int lane = threadIdx.x & 31;
    if (n >= N_NODES) return;
    float v = g_out2[(size_t)n * F2 + lane] / g_den2[n] + __ldg(&b2[lane]);
    float m = v;
#pragma unroll
    for (int o = 16; o; o >>= 1) m = fmaxf(m, __shfl_xor_sync(FULL, m, o));
    float ex = expf(v - m);
    float s = ex;
#pragma unroll
    for (int o = 16; o; o >>= 1) s += __shfl_xor_sync(FULL, s, o);
    float ls = v - m - logf(s);
    out[(size_t)n * F2 + lane] = v;
    out[(size_t)N_NODES * F2 + (size_t)n * F2 + lane] = ls;
}

// ---------------- launcher ----------------
extern "C" void kernel_launch(void* const* d_in, const int* in_sizes, int n_in,
                              void* d_out, int out_size) {
    const float* x    = (const float*)d_in[0];
    const int*   ei   = (const int*)d_in[1];     // dtype detected at runtime
    const float* W1l  = (const float*)d_in[2];
    const float* W1r  = (const float*)d_in[3];
    const float* att1 = (const float*)d_in[4];
    const float* b1   = (const float*)d_in[5];
    const float* W2l  = (const float*)d_in[6];
    const float* W2r  = (const float*)d_in[7];
    const float* att2 = (const float*)d_in[8];
    const float* b2   = (const float*)d_in[9];
    float* out = (float*)d_out;

    int warps_g = ((N_NODES + 7) / 8) * 2;  // 8 nodes per warp, 2 matrices

    k_init<<<(N_NODES * F1 + 255) / 256, 256>>>();
    k_detect<<<512, 256>>>(ei);
    k_convert_all<<<(E_TOT + 255) / 256, 256>>>(ei);
    k_gemm1<<<(warps_g * 32 + 255) / 256, 256>>>(x, W1l, W1r);
    k_edge1<<<(E_TOT * 32) / 256, 256>>>(att1);
    k_gemm2<<<(warps_g * 32 + 255) / 256, 256>>>(W2l, W2r, b1);
    k_edge2<<<(((E_TOT + 3) / 4) * 32 + 255) / 256, 256>>>(att2);
    k_final<<<(N_NODES * 32 + 255) / 256, 256>>>(b2, out);
}

// round 6
// speedup vs baseline: 2.1673x; 1.0952x over previous
#include <cuda_runtime.h>
#include <cstdint>
#include <float.h>

#define N_NODES 50000
#define E_RAW   800000
#define E_TOT   850000   // E_RAW + N_NODES self loops
#define H1      15
#define F1      120      // H1*8
#define DIN     128
#define F2      32

#define FULL 0xFFFFFFFFu

// ---------------- scratch (device globals; no allocation allowed) ----------------
__device__ int      g_src[(size_t)E_TOT];
__device__ int      g_dst[(size_t)E_TOT];
__device__ int      g_cnt[(size_t)N_NODES];
__device__ int      g_cursor[(size_t)N_NODES];
__device__ int      g_rowstart[(size_t)N_NODES + 1];
__device__ int      g_csr_src[(size_t)E_TOT];
__device__ unsigned g_is64;                            // edge dtype flag
__device__ float    g_xl1[(size_t)N_NODES * F1];
__device__ float    g_xr1[(size_t)N_NODES * F1];
__device__ float    g_h[(size_t)N_NODES * F1];         // layer-1 activations (post ELU)
__device__ float    g_hl2[(size_t)N_NODES * F2];
__device__ float    g_hr2[(size_t)N_NODES * F2];

__device__ __forceinline__ float lrelu(float v) { return v > 0.f ? v : 0.2f * v; }

// ---------------- edge dtype detection ----------------
// int64 edges (<50000): every odd 32-bit word is 0. int32 edges: odd words ~random ids.
__global__ void k_detect(const int* __restrict__ ei_raw) {
    unsigned acc = 0;
    for (int i = blockIdx.x * blockDim.x + threadIdx.x; i < E_RAW; i += gridDim.x * blockDim.x)
        acc |= (unsigned)ei_raw[2 * i + 1];
#pragma unroll
    for (int o = 16; o; o >>= 1) acc |= __shfl_xor_sync(FULL, acc, o);
    if ((threadIdx.x & 31) == 0 && acc) atomicOr(&g_is64, 1u);
}

// ---------------- init ----------------
__global__ void k_init() {
    int i = blockIdx.x * blockDim.x + threadIdx.x;
    if (i == 0) g_is64 = 0u;
    if (i < N_NODES) { g_cnt[i] = 0; g_cursor[i] = 0; }
}

// ---------------- normalize edges to int32 + self loops + degree count ----------------
__global__ void k_convert_count(const int* __restrict__ ei_raw) {
    int e = blockIdx.x * blockDim.x + threadIdx.x;
    if (e >= E_TOT) return;
    int src, dst;
    if (e >= E_RAW) {
        src = dst = e - E_RAW;
    } else if (g_is64) {           // flag set -> data is int32
        src = ei_raw[e];
        dst = ei_raw[E_RAW + e];
    } else {                       // int64 data: low word at 2*index
        src = ei_raw[2 * e];
        dst = ei_raw[2 * (E_RAW + e)];
    }
    g_src[e] = src;
    g_dst[e] = dst;
    atomicAdd(&g_cnt[dst], 1);
}

// ---------------- single-block exclusive scan over degrees ----------------
__global__ void k_scan() {
    __shared__ int part[1024];
    int t = threadIdx.x;
    const int PER = (N_NODES + 1023) / 1024;   // 49
    int base = t * PER;
    int s = 0;
    for (int i = 0; i < PER; i++) {
        int idx = base + i;
        if (idx < N_NODES) s += g_cnt[idx];
    }
    part[t] = s;
    __syncthreads();
    for (int off = 1; off < 1024; off <<= 1) {
        int v = (t >= off) ? part[t - off] : 0;
        __syncthreads();
        part[t] += v;
        __syncthreads();
    }
    int run = (t == 0) ? 0 : part[t - 1];
    for (int i = 0; i < PER; i++) {
        int idx = base + i;
        if (idx < N_NODES) { g_rowstart[idx] = run; run += g_cnt[idx]; }
    }
    if (t == 1023) g_rowstart[N_NODES] = run;
}

// ---------------- fill CSR (src ids grouped by dst) ----------------
__global__ void k_fill() {
    int e = blockIdx.x * blockDim.x + threadIdx.x;
    if (e >= E_TOT) return;
    int dst = g_dst[e];
    int pos = g_rowstart[dst] + atomicAdd(&g_cursor[dst], 1);
    g_csr_src[pos] = g_src[e];
}

// ---------------- GEMM1: smem x-tile, warp = 8 nodes x ONE matrix ----------------
__global__ void k_gemm1(const float* __restrict__ x,
                        const float* __restrict__ Wl,
                        const float* __restrict__ Wr) {
    __shared__ float4 sx[32 * 32];              // 32 nodes x 128 floats = 16KB
    int tid = threadIdx.x;
    int nb0 = blockIdx.x * 32;

    const float4* x4 = (const float4*)x + (size_t)nb0 * 32;
    for (int i = tid; i < 32 * 32; i += 256)
        if (nb0 + (i >> 5) < N_NODES) sx[i] = x4[i];
    __syncthreads();

    int w = tid >> 5, lane = tid & 31;
    int mat = w & 1;
    int l0 = (w >> 1) * 8;
    int nb = nb0 + l0;
    if (nb >= N_NODES) return;                  // N % 8 == 0 -> whole group valid

    const float4* w4 = (const float4*)(mat ? Wr : Wl);   // row k -> k*30 + g
    float* outp = mat ? g_xr1 : g_xl1;
    int g = lane < 30 ? lane : 0;               // lanes 30,31 compute garbage, never store

    float4 acc[8];
#pragma unroll
    for (int j = 0; j < 8; j++) acc[j] = make_float4(0, 0, 0, 0);

    for (int kq = 0; kq < 32; kq++) {
        float4 w0 = __ldg(&w4[(size_t)(kq * 4 + 0) * 30 + g]);
        float4 w1 = __ldg(&w4[(size_t)(kq * 4 + 1) * 30 + g]);
        float4 w2 = __ldg(&w4[(size_t)(kq * 4 + 2) * 30 + g]);
        float4 w3 = __ldg(&w4[(size_t)(kq * 4 + 3) * 30 + g]);
#pragma unroll
        for (int j = 0; j < 8; j++) {
            float4 xj = sx[(l0 + j) * 32 + kq];   // broadcast LDS.128
            acc[j].x += xj.x * w0.x + xj.y * w1.x + xj.z * w2.x + xj.w * w3.x;
            acc[j].y += xj.x * w0.y + xj.y * w1.y + xj.z * w2.y + xj.w * w3.y;
            acc[j].z += xj.x * w0.z + xj.y * w1.z + xj.z * w2.z + xj.w * w3.z;
            acc[j].w += xj.x * w0.w + xj.y * w1.w + xj.z * w2.w + xj.w * w3.w;
        }
    }
    if (lane < 30) {
#pragma unroll
        for (int j = 0; j < 8; j++)
            *(float4*)(outp + (size_t)(nb + j) * F1 + lane * 4) = acc[j];
    }
}

// ---------------- layer1 aggregate: warp per dst node, CSR, fully fused ----------------
// acc = sum_e exp(<lrelu(xl[src]+xr[dst]),att>) * xl[src]; then /den + bias, ELU -> g_h
__global__ void k_agg1(const float* __restrict__ att, const float* __restrict__ b1) {
    int dst = (blockIdx.x * blockDim.x + threadIdx.x) >> 5;
    int lane = threadIdx.x & 31;
    if (dst >= N_NODES) return;
    int g = lane < 30 ? lane : 0;

    float4 b = *((const float4*)(g_xr1 + (size_t)dst * F1) + g);
    float4 at = __ldg((const float4*)att + g);
    int s0 = g_rowstart[dst], s1 = g_rowstart[dst + 1];

    float4 acc = make_float4(0, 0, 0, 0);
    float den = 0.f;
    for (int i = s0; i < s1; i++) {
        int src = g_csr_src[i];                 // uniform across warp
        float4 a = __ldg((const float4*)(g_xl1 + (size_t)src * F1) + g);
        float p = lrelu(a.x + b.x) * at.x + lrelu(a.y + b.y) * at.y +
                  lrelu(a.z + b.z) * at.z + lrelu(a.w + b.w) * at.w;
        float p2 = __shfl_down_sync(FULL, p, 1);
        float ee = expf(p + p2);                // head value valid on even lanes < 30
        float w = __shfl_sync(FULL, ee, lane & 30);
        acc.x += w * a.x; acc.y += w * a.y; acc.z += w * a.z; acc.w += w * a.w;
        if ((lane & 1) == 0) den += ee;
    }
    float d = __shfl_sync(FULL, den, lane & 30);
    if (lane < 30) {
        float4 bv = __ldg((const float4*)b1 + g);
        float inv = 1.f / d;
        float4 v;
        v.x = acc.x * inv + bv.x; v.y = acc.y * inv + bv.y;
        v.z = acc.z * inv + bv.z; v.w = acc.w * inv + bv.w;
        v.x = v.x > 0.f ? v.x : expm1f(v.x);
        v.y = v.y > 0.f ? v.y : expm1f(v.y);
        v.z = v.z > 0.f ? v.z : expm1f(v.z);
        v.w = v.w > 0.f ? v.w : expm1f(v.w);
        *(float4*)(g_h + (size_t)dst * F1 + lane * 4) = v;
    }
}

// ---------------- GEMM2: smem x-tile, warp = 8 nodes x ONE matrix, lane = col ----------------
__global__ void k_gemm2(const float* __restrict__ Wl, const float* __restrict__ Wr) {
    __shared__ float4 sx[32 * 30];              // 32 nodes x 120 floats = 15.4KB
    int tid = threadIdx.x;
    int nb0 = blockIdx.x * 32;

    const float4* h4 = (const float4*)g_h + (size_t)nb0 * 30;
    for (int i = tid; i < 32 * 30; i += 256)
        if (nb0 + i / 30 < N_NODES) sx[i] = h4[i];
    __syncthreads();

    int w = tid >> 5, lane = tid & 31;
    int mat = w & 1;
    int l0 = (w >> 1) * 8;
    int nb = nb0 + l0;
    if (nb >= N_NODES) return;

    const float* W = mat ? Wr : Wl;             // [F1, F2] row-major, lane = col
    float* outp = mat ? g_hr2 : g_hl2;

    float acc[8] = {0, 0, 0, 0, 0, 0, 0, 0};
    for (int kq = 0; kq < 30; kq++) {
        float w0 = __ldg(&W[(size_t)(kq * 4 + 0) * F2 + lane]);
        float w1 = __ldg(&W[(size_t)(kq * 4 + 1) * F2 + lane]);
        float w2 = __ldg(&W[(size_t)(kq * 4 + 2) * F2 + lane]);
        float w3 = __ldg(&W[(size_t)(kq * 4 + 3) * F2 + lane]);
#pragma unroll
        for (int j = 0; j < 8; j++) {
            float4 xj = sx[(l0 + j) * 30 + kq];
            acc[j] += xj.x * w0 + xj.y * w1 + xj.z * w2 + xj.w * w3;
        }
    }
#pragma unroll
    for (int j = 0; j < 8; j++)
        outp[(size_t)(nb + j) * F2 + lane] = acc[j];
}

// ---------------- layer2 aggregate + bias + log_softmax: warp per dst node ----------------
__global__ void k_agg2(const float* __restrict__ att2, const float* __restrict__ b2,
                       float* __restrict__ out) {
    int dst = (blockIdx.x * blockDim.x + threadIdx.x) >> 5;
    int lane = threadIdx.x & 31;
    if (dst >= N_NODES) return;

    float b = g_hr2[(size_t)dst * F2 + lane];
    float at = __ldg(&att2[lane]);
    int s0 = g_rowstart[dst], s1 = g_rowstart[dst + 1];

    float acc = 0.f, den = 0.f;
    for (int i = s0; i < s1; i++) {
        int src = g_csr_src[i];
        float a = g_hl2[(size_t)src * F2 + lane];
        float t = lrelu(a + b) * at;
#pragma unroll
        for (int o = 16; o; o >>= 1) t += __shfl_xor_sync(FULL, t, o);
        float w = expf(t);                      // identical on all lanes
        den += w;
        acc += w * a;
    }
    float v = acc / den + __ldg(&b2[lane]);
    float m = v;
#pragma unroll
    for (int o = 16; o; o >>= 1) m = fmaxf(m, __shfl_xor_sync(FULL, m, o));
    float ex = expf(v - m);
    float s = ex;
#pragma unroll
    for (int o = 16; o; o >>= 1) s += __shfl_xor_sync(FULL, s, o);
    float ls = v - m - logf(s);
    out[(size_t)dst * F2 + lane] = v;
    out[(size_t)N_NODES * F2 + (size_t)dst * F2 + lane] = ls;
}

// ---------------- launcher ----------------
extern "C" void kernel_launch(void* const* d_in, const int* in_sizes, int n_in,
                              void* d_out, int out_size) {
    const float* x    = (const float*)d_in[0];
    const int*   ei   = (const int*)d_in[1];     // dtype detected at runtime
    const float* W1l  = (const float*)d_in[2];
    const float* W1r  = (const float*)d_in[3];
    const float* att1 = (const float*)d_in[4];
    const float* b1   = (const float*)d_in[5];
    const float* W2l  = (const float*)d_in[6];
    const float* W2r  = (const float*)d_in[7];
    const float* att2 = (const float*)d_in[8];
    const float* b2   = (const float*)d_in[9];
    float* out = (float*)d_out;

    int gblocks = (N_NODES + 31) / 32;           // 1563

    k_init<<<(N_NODES + 255) / 256, 256>>>();
    k_detect<<<512, 256>>>(ei);
    k_convert_count<<<(E_TOT + 255) / 256, 256>>>(ei);
    k_scan<<<1, 1024>>>();
    k_fill<<<(E_TOT + 255) / 256, 256>>>();
    k_gemm1<<<gblocks, 256>>>(x, W1l, W1r);
    k_agg1<<<(N_NODES * 32 + 255) / 256, 256>>>(att1, b1);
    k_gemm2<<<gblocks, 256>>>(W2l, W2r);
    k_agg2<<<(N_NODES * 32 + 255) / 256, 256>>>(att2, b2, out);
}

// round 7
// speedup vs baseline: 2.4949x; 1.1511x over previous
#include <cuda_runtime.h>
#include <cstdint>
#include <float.h>

#define N_NODES 50000
#define E_RAW   800000
#define E_TOT   850000   // E_RAW + N_NODES self loops
#define H1      15
#define F1      120      // H1*8
#define DIN     128
#define F2      32

#define FULL 0xFFFFFFFFu
#define NSCAN_BLK 98     // ceil(N_NODES / 512)

// ---------------- scratch (device globals; no allocation allowed) ----------------
__device__ int      g_src[(size_t)E_TOT];
__device__ int      g_dst[(size_t)E_TOT];
__device__ int      g_cnt[(size_t)N_NODES];
__device__ int      g_cursor[(size_t)N_NODES];
__device__ int      g_rowstart[(size_t)N_NODES + 1];
__device__ int      g_csr_src[(size_t)E_TOT];
__device__ int      g_part[128];
__device__ int      g_partoff[128];
__device__ unsigned g_is64;                            // edge dtype flag
__device__ float    g_xl1[(size_t)N_NODES * F1];
__device__ float    g_xr1[(size_t)N_NODES * F1];
__device__ float    g_h[(size_t)N_NODES * F1];         // layer-1 activations (post ELU)
__device__ float    g_hl2[(size_t)N_NODES * F2];
__device__ float    g_hr2[(size_t)N_NODES * F2];

__device__ __forceinline__ float lrelu(float v) { return v > 0.f ? v : 0.2f * v; }

// ---------------- edge dtype detection (sampled; 1 block) ----------------
// int64 edges (<50000): every odd 32-bit word is 0. int32 edges: odd words are
// random node ids; P[4096 sampled words all zero] ~ (1/50000)^4096 ~ 0.
__global__ void k_detect(const int* __restrict__ ei_raw) {
    unsigned acc = 0;
    for (int i = threadIdx.x; i < 4096; i += 256)
        acc |= (unsigned)ei_raw[2 * i + 1];
#pragma unroll
    for (int o = 16; o; o >>= 1) acc |= __shfl_xor_sync(FULL, acc, o);
    if ((threadIdx.x & 31) == 0 && acc) atomicOr(&g_is64, 1u);
}

// ---------------- init ----------------
__global__ void k_init() {
    int i = blockIdx.x * blockDim.x + threadIdx.x;
    if (i == 0) g_is64 = 0u;
    if (i < N_NODES) { g_cnt[i] = 0; g_cursor[i] = 0; }
}

// ---------------- normalize edges to int32 + self loops + degree count ----------------
__global__ void k_convert_count(const int* __restrict__ ei_raw) {
    int e = blockIdx.x * blockDim.x + threadIdx.x;
    if (e >= E_TOT) return;
    int src, dst;
    if (e >= E_RAW) {
        src = dst = e - E_RAW;
    } else if (g_is64) {           // flag set -> data is int32
        src = ei_raw[e];
        dst = ei_raw[E_RAW + e];
    } else {                       // int64 data: low word at 2*index
        src = ei_raw[2 * e];
        dst = ei_raw[2 * (E_RAW + e)];
    }
    g_src[e] = src;
    g_dst[e] = dst;
    atomicAdd(&g_cnt[dst], 1);
}

// ---------------- parallel scan: pass A (block partial sums) ----------------
__global__ void k_scan_a() {
    int idx = blockIdx.x * 512 + threadIdx.x;
    int v = (idx < N_NODES) ? g_cnt[idx] : 0;
#pragma unroll
    for (int o = 16; o; o >>= 1) v += __shfl_down_sync(FULL, v, o);
    __shared__ int ws[16];
    if ((threadIdx.x & 31) == 0) ws[threadIdx.x >> 5] = v;
    __syncthreads();
    if (threadIdx.x < 16) {
        int s = ws[threadIdx.x];
#pragma unroll
        for (int o = 8; o; o >>= 1) s += __shfl_down_sync(0xFFFFu, s, o);
        if (threadIdx.x == 0) g_part[blockIdx.x] = s;
    }
}

// ---------------- parallel scan: pass B (scan 98 partials; 1 block x 128) ----------------
__global__ void k_scan_b() {
    int t = threadIdx.x;                       // 128 threads
    int v = (t < NSCAN_BLK) ? g_part[t] : 0;
    int lane = t & 31, wid = t >> 5;
    int inc = v;
#pragma unroll
    for (int o = 1; o < 32; o <<= 1) {
        int u = __shfl_up_sync(FULL, inc, o);
        if (lane >= o) inc += u;
    }
    __shared__ int ws[4];
    if (lane == 31) ws[wid] = inc;
    __syncthreads();
    int woff = 0;
    for (int i = 0; i < wid; i++) woff += ws[i];
    g_partoff[t] = inc - v + woff;             // exclusive
    if (t == 0) g_rowstart[N_NODES] = E_TOT;
}

// ---------------- parallel scan: pass C (block exclusive scan + offset) ----------------
__global__ void k_scan_c() {
    int idx = blockIdx.x * 512 + threadIdx.x;
    int v = (idx < N_NODES) ? g_cnt[idx] : 0;
    int lane = threadIdx.x & 31, wid = threadIdx.x >> 5;
    int inc = v;
#pragma unroll
    for (int o = 1; o < 32; o <<= 1) {
        int u = __shfl_up_sync(FULL, inc, o);
        if (lane >= o) inc += u;
    }
    __shared__ int ws[16];
    if (lane == 31) ws[wid] = inc;
    __syncthreads();
    if (threadIdx.x < 16) {
        int s = ws[threadIdx.x];
#pragma unroll
        for (int o = 1; o < 16; o <<= 1) {
            int u = __shfl_up_sync(0xFFFFu, s, o);
            if (threadIdx.x >= o) s += u;
        }
        ws[threadIdx.x] = s;
    }
    __syncthreads();
    int woff = wid ? ws[wid - 1] : 0;
    if (idx < N_NODES)
        g_rowstart[idx] = inc - v + woff + g_partoff[blockIdx.x];
}

// ---------------- fill CSR (src ids grouped by dst) ----------------
__global__ void k_fill() {
    int e = blockIdx.x * blockDim.x + threadIdx.x;
    if (e >= E_TOT) return;
    int dst = g_dst[e];
    int pos = g_rowstart[dst] + atomicAdd(&g_cursor[dst], 1);
    g_csr_src[pos] = g_src[e];
}

// ---------------- GEMM1: smem x-tile, warp = 8 nodes x ONE matrix ----------------
__global__ void k_gemm1(const float* __restrict__ x,
                        const float* __restrict__ Wl,
                        const float* __restrict__ Wr) {
    __shared__ float4 sx[32 * 32];              // 32 nodes x 128 floats = 16KB
    int tid = threadIdx.x;
    int nb0 = blockIdx.x * 32;

    const float4* x4 = (const float4*)x + (size_t)nb0 * 32;
    for (int i = tid; i < 32 * 32; i += 256)
        if (nb0 + (i >> 5) < N_NODES) sx[i] = x4[i];
    __syncthreads();

    int w = tid >> 5, lane = tid & 31;
    int mat = w & 1;
    int l0 = (w >> 1) * 8;
    int nb = nb0 + l0;
    if (nb >= N_NODES) return;                  // N % 8 == 0 -> whole group valid

    const float4* w4 = (const float4*)(mat ? Wr : Wl);   // row k -> k*30 + g
    float* outp = mat ? g_xr1 : g_xl1;
    int g = lane < 30 ? lane : 0;               // lanes 30,31 compute garbage, never store

    float4 acc[8];
#pragma unroll
    for (int j = 0; j < 8; j++) acc[j] = make_float4(0, 0, 0, 0);

    for (int kq = 0; kq < 32; kq++) {
        float4 w0 = __ldg(&w4[(size_t)(kq * 4 + 0) * 30 + g]);
        float4 w1 = __ldg(&w4[(size_t)(kq * 4 + 1) * 30 + g]);
        float4 w2 = __ldg(&w4[(size_t)(kq * 4 + 2) * 30 + g]);
        float4 w3 = __ldg(&w4[(size_t)(kq * 4 + 3) * 30 + g]);
#pragma unroll
        for (int j = 0; j < 8; j++) {
            float4 xj = sx[(l0 + j) * 32 + kq];   // broadcast LDS.128
            acc[j].x += xj.x * w0.x + xj.y * w1.x + xj.z * w2.x + xj.w * w3.x;
            acc[j].y += xj.x * w0.y + xj.y * w1.y + xj.z * w2.y + xj.w * w3.y;
            acc[j].z += xj.x * w0.z + xj.y * w1.z + xj.z * w2.z + xj.w * w3.z;
            acc[j].w += xj.x * w0.w + xj.y * w1.w + xj.z * w2.w + xj.w * w3.w;
        }
    }
    if (lane < 30) {
#pragma unroll
        for (int j = 0; j < 8; j++)
            *(float4*)(outp + (size_t)(nb + j) * F1 + lane * 4) = acc[j];
    }
}

// ---------------- layer1 aggregate: warp per dst node, CSR, fully fused ----------------
// acc = sum_e exp(<lrelu(xl[src]+xr[dst]),att>) * xl[src]; then /den + bias, ELU -> g_h
__global__ void k_agg1(const float* __restrict__ att, const float* __restrict__ b1) {
    int dst = (blockIdx.x * blockDim.x + threadIdx.x) >> 5;
    int lane = threadIdx.x & 31;
    if (dst >= N_NODES) return;
    int g = lane < 30 ? lane : 0;

    float4 b = *((const float4*)(g_xr1 + (size_t)dst * F1) + g);
    float4 at = __ldg((const float4*)att + g);
    int s0 = g_rowstart[dst], s1 = g_rowstart[dst + 1];

    float4 acc = make_float4(0, 0, 0, 0);
    float den = 0.f;
    for (int i = s0; i < s1; i++) {
        int src = g_csr_src[i];                 // uniform across warp
        float4 a = __ldg((const float4*)(g_xl1 + (size_t)src * F1) + g);
        float p = lrelu(a.x + b.x) * at.x + lrelu(a.y + b.y) * at.y +
                  lrelu(a.z + b.z) * at.z + lrelu(a.w + b.w) * at.w;
        float p2 = __shfl_down_sync(FULL, p, 1);
        float ee = expf(p + p2);                // head value valid on even lanes < 30
        float w = __shfl_sync(FULL, ee, lane & 30);
        acc.x += w * a.x; acc.y += w * a.y; acc.z += w * a.z; acc.w += w * a.w;
        if ((lane & 1) == 0) den += ee;
    }
    float d = __shfl_sync(FULL, den, lane & 30);
    if (lane < 30) {
        float4 bv = __ldg((const float4*)b1 + g);
        float inv = 1.f / d;
        float4 v;
        v.x = acc.x * inv + bv.x; v.y = acc.y * inv + bv.y;
        v.z = acc.z * inv + bv.z; v.w = acc.w * inv + bv.w;
        v.x = v.x > 0.f ? v.x : expm1f(v.x);
        v.y = v.y > 0.f ? v.y : expm1f(v.y);
        v.z = v.z > 0.f ? v.z : expm1f(v.z);
        v.w = v.w > 0.f ? v.w : expm1f(v.w);
        *(float4*)(g_h + (size_t)dst * F1 + lane * 4) = v;
    }
}

// ---------------- GEMM2: smem x-tile, warp = 8 nodes x ONE matrix, lane = col ----------------
__global__ void k_gemm2(const float* __restrict__ Wl, const float* __restrict__ Wr) {
    __shared__ float4 sx[32 * 30];              // 32 nodes x 120 floats = 15.4KB
    int tid = threadIdx.x;
    int nb0 = blockIdx.x * 32;

    const float4* h4 = (const float4*)g_h + (size_t)nb0 * 30;
    for (int i = tid; i < 32 * 30; i += 256)
        if (nb0 + i / 30 < N_NODES) sx[i] = h4[i];
    __syncthreads();

    int w = tid >> 5, lane = tid & 31;
    int mat = w & 1;
    int l0 = (w >> 1) * 8;
    int nb = nb0 + l0;
    if (nb >= N_NODES) return;

    const float* W = mat ? Wr : Wl;             // [F1, F2] row-major, lane = col
    float* outp = mat ? g_hr2 : g_hl2;

    float acc[8] = {0, 0, 0, 0, 0, 0, 0, 0};
    for (int kq = 0; kq < 30; kq++) {
        float w0 = __ldg(&W[(size_t)(kq * 4 + 0) * F2 + lane]);
        float w1 = __ldg(&W[(size_t)(kq * 4 + 1) * F2 + lane]);
        float w2 = __ldg(&W[(size_t)(kq * 4 + 2) * F2 + lane]);
        float w3 = __ldg(&W[(size_t)(kq * 4 + 3) * F2 + lane]);
#pragma unroll
        for (int j = 0; j < 8; j++) {
            float4 xj = sx[(l0 + j) * 30 + kq];
            acc[j] += xj.x * w0 + xj.y * w1 + xj.z * w2 + xj.w * w3;
        }
    }
#pragma unroll
    for (int j = 0; j < 8; j++)
        outp[(size_t)(nb + j) * F2 + lane] = acc[j];
}

// ---------------- layer2 aggregate + bias + log_softmax: warp per dst node ----------------
__global__ void k_agg2(const float* __restrict__ att2, const float* __restrict__ b2,
                       float* __restrict__ out) {
    int dst = (blockIdx.x * blockDim.x + threadIdx.x) >> 5;
    int lane = threadIdx.x & 31;
    if (dst >= N_NODES) return;

    float b = g_hr2[(size_t)dst * F2 + lane];
    float at = __ldg(&att2[lane]);
    int s0 = g_rowstart[dst], s1 = g_rowstart[dst + 1];

    float acc = 0.f, den = 0.f;
    for (int i = s0; i < s1; i++) {
        int src = g_csr_src[i];
        float a = g_hl2[(size_t)src * F2 + lane];
        float t = lrelu(a + b) * at;
#pragma unroll
        for (int o = 16; o; o >>= 1) t += __shfl_xor_sync(FULL, t, o);
        float w = expf(t);                      // identical on all lanes
        den += w;
        acc += w * a;
    }
    float v = acc / den + __ldg(&b2[lane]);
    float m = v;
#pragma unroll
    for (int o = 16; o; o >>= 1) m = fmaxf(m, __shfl_xor_sync(FULL, m, o));
    float ex = expf(v - m);
    float s = ex;
#pragma unroll
    for (int o = 16; o; o >>= 1) s += __shfl_xor_sync(FULL, s, o);
    float ls = v - m - logf(s);
    out[(size_t)dst * F2 + lane] = v;
    out[(size_t)N_NODES * F2 + (size_t)dst * F2 + lane] = ls;
}

// ---------------- launcher ----------------
extern "C" void kernel_launch(void* const* d_in, const int* in_sizes, int n_in,
                              void* d_out, int out_size) {
    const float* x    = (const float*)d_in[0];
    const int*   ei   = (const int*)d_in[1];     // dtype detected at runtime
    const float* W1l  = (const float*)d_in[2];
    const float* W1r  = (const float*)d_in[3];
    const float* att1 = (const float*)d_in[4];
    const float* b1   = (const float*)d_in[5];
    const float* W2l  = (const float*)d_in[6];
    const float* W2r  = (const float*)d_in[7];
    const float* att2 = (const float*)d_in[8];
    const float* b2   = (const float*)d_in[9];
    float* out = (float*)d_out;

    int gblocks = (N_NODES + 31) / 32;           // 1563

    k_init<<<(N_NODES + 255) / 256, 256>>>();
    k_detect<<<1, 256>>>(ei);
    k_convert_count<<<(E_TOT + 255) / 256, 256>>>(ei);
    k_scan_a<<<NSCAN_BLK, 512>>>();
    k_scan_b<<<1, 128>>>();
    k_scan_c<<<NSCAN_BLK, 512>>>();
    k_fill<<<(E_TOT + 255) / 256, 256>>>();
    k_gemm1<<<gblocks, 256>>>(x, W1l, W1r);
    k_agg1<<<(N_NODES * 32 + 255) / 256, 256>>>(att1, b1);
    k_gemm2<<<gblocks, 256>>>(W2l, W2r);
    k_agg2<<<(N_NODES * 32 + 255) / 256, 256>>>(att2, b2, out);
}